// round 2
// baseline (speedup 1.0000x reference)
#include <cuda_runtime.h>
#include <cuda_bf16.h>
#include <math.h>

#define N_NODES 100000
#define N_EDGES 400000
#define D 128
#define N_GRAPHS 4096
#define N_LAYERS 5
#define IN_FEAT 11

// ---------------- scratch (device globals; no allocations) ----------------
__device__ float g_h[N_NODES * D];
__device__ float g_t[N_NODES * D];
__device__ float g_dinv[N_NODES];
__device__ float g_eval[N_EDGES];
__device__ int   g_cnt[N_NODES];
__device__ int   g_fill[N_NODES];
__device__ int   g_rowptr[N_NODES + 1];
__device__ int   g_col[N_EDGES];

// ---------------- preprocessing ----------------
__global__ void k_zero_int() {
    int i = blockIdx.x * blockDim.x + threadIdx.x;
    if (i < N_NODES) { g_cnt[i] = 0; g_fill[i] = 0; }
}

__global__ void k_hist(const int* __restrict__ ei) {
    int e = blockIdx.x * blockDim.x + threadIdx.x;
    if (e < N_EDGES) {
        int d = ei[N_EDGES + e];   // dst
        atomicAdd(&g_cnt[d], 1);
    }
}

__global__ void k_dinv() {
    int i = blockIdx.x * blockDim.x + threadIdx.x;
    if (i < N_NODES) g_dinv[i] = rsqrtf((float)g_cnt[i] + 2.0f);
}

// single-block exclusive scan of g_cnt -> g_rowptr
__global__ void k_scan() {
    __shared__ int sums[1024];
    int t = threadIdx.x;
    const int chunk = (N_NODES + 1023) / 1024;
    int start = t * chunk;
    int end = start + chunk; if (end > N_NODES) end = N_NODES;
    int s = 0;
    for (int i = start; i < end; i++) s += g_cnt[i];
    sums[t] = s;
    __syncthreads();
    for (int off = 1; off < 1024; off <<= 1) {
        int v = 0;
        if (t >= off) v = sums[t - off];
        __syncthreads();
        if (t >= off) sums[t] += v;
        __syncthreads();
    }
    int excl = (t == 0) ? 0 : sums[t - 1];
    for (int i = start; i < end; i++) { g_rowptr[i] = excl; excl += g_cnt[i]; }
    if (t == 1023) g_rowptr[N_NODES] = sums[1023];
}

__global__ void k_scatter(const int* __restrict__ ei) {
    int e = blockIdx.x * blockDim.x + threadIdx.x;
    if (e < N_EDGES) {
        int s = ei[e];
        int d = ei[N_EDGES + e];
        int pos = g_rowptr[d] + atomicAdd(&g_fill[d], 1);
        g_col[pos]  = s;
        g_eval[pos] = g_dinv[s] * g_dinv[d];
    }
}

// ---------------- expansion: h = log1p(x) @ We + be ----------------
__global__ void k_expand(const float* __restrict__ x,
                         const float* __restrict__ We,
                         const float* __restrict__ be) {
    __shared__ float sW[IN_FEAT * D];
    __shared__ float lx[IN_FEAT];
    int d = threadIdx.x;
    #pragma unroll
    for (int k = 0; k < IN_FEAT; k++) sW[k * D + d] = We[k * D + d];
    float bias = be[d];
    for (int i = blockIdx.x; i < N_NODES; i += gridDim.x) {
        if (d < IN_FEAT) lx[d] = log1pf(x[i * IN_FEAT + d]);
        __syncthreads();
        float acc = bias;
        #pragma unroll
        for (int k = 0; k < IN_FEAT; k++) acc = fmaf(lx[k], sW[k * D + d], acc);
        g_h[i * D + d] = acc;
        __syncthreads();
    }
}

// ---------------- GEMM: t = h @ W (M=100000, N=128, K=128, fp32) ----------
// block: 256 threads; tile: 64 rows x 128 cols; thread: 8 rows x 4 cols
__global__ __launch_bounds__(256) void k_gemm(const float* __restrict__ W) {
    extern __shared__ float sm[];
    float* Ws = sm;            // 128*128
    float* Hs = sm + D * D;    // 64*128
    int tid = threadIdx.x;
    int tx = tid & 31, ty = tid >> 5;

    float4* Ws4 = (float4*)Ws;
    const float4* W4 = (const float4*)W;
    #pragma unroll 4
    for (int i = tid; i < D * D / 4; i += 256) Ws4[i] = W4[i];

    int row0 = blockIdx.x * 64;
    float4* Hs4 = (float4*)Hs;
    const float4* H4 = (const float4*)g_h;
    #pragma unroll 4
    for (int i = tid; i < 64 * D / 4; i += 256) {
        int r = i >> 5, c = i & 31;
        int gr = row0 + r;
        Hs4[i] = (gr < N_NODES) ? H4[gr * 32 + c] : make_float4(0.f, 0.f, 0.f, 0.f);
    }
    __syncthreads();

    float acc[8][4];
    #pragma unroll
    for (int i = 0; i < 8; i++)
        #pragma unroll
        for (int j = 0; j < 4; j++) acc[i][j] = 0.f;

    #pragma unroll 4
    for (int k = 0; k < D; k++) {
        float4 w = Ws4[k * 32 + tx];
        #pragma unroll
        for (int i = 0; i < 8; i++) {
            float a = Hs[(ty * 8 + i) * D + k];
            acc[i][0] = fmaf(a, w.x, acc[i][0]);
            acc[i][1] = fmaf(a, w.y, acc[i][1]);
            acc[i][2] = fmaf(a, w.z, acc[i][2]);
            acc[i][3] = fmaf(a, w.w, acc[i][3]);
        }
    }

    float4* T4 = (float4*)g_t;
    #pragma unroll
    for (int i = 0; i < 8; i++) {
        int gr = row0 + ty * 8 + i;
        if (gr < N_NODES)
            T4[gr * 32 + tx] = make_float4(acc[i][0], acc[i][1], acc[i][2], acc[i][3]);
    }
}

// ---------------- aggregate: h += relu(self + neighbor sum + bias) --------
__global__ void k_aggregate(const float* __restrict__ bgl) {
    int i = blockIdx.x;
    int d = threadIdx.x;
    float dv = g_dinv[i];
    float acc = bgl[d] + 2.0f * dv * dv * g_t[i * D + d];
    int s0 = g_rowptr[i], s1 = g_rowptr[i + 1];
    for (int e = s0; e < s1; e++) {
        acc = fmaf(g_eval[e], g_t[g_col[e] * D + d], acc);
    }
    g_h[i * D + d] += fmaxf(acc, 0.f);
}

// ---------------- pooling ----------------
__global__ void k_zero_out(float* __restrict__ out, int n) {
    int i = blockIdx.x * blockDim.x + threadIdx.x;
    if (i < n) out[i] = 0.f;
}

#define NODES_PER_BLOCK 16
__global__ void k_pool(const int* __restrict__ batch, float* __restrict__ out) {
    int n0 = blockIdx.x * NODES_PER_BLOCK;
    int d = threadIdx.x;
    float acc = 0.f;
    int curg = -1;
    for (int j = 0; j < NODES_PER_BLOCK; j++) {
        int i = n0 + j;
        if (i >= N_NODES) break;
        int g = batch[i];
        if (g != curg) {
            if (curg >= 0) atomicAdd(&out[curg * D + d], acc);
            curg = g; acc = 0.f;
        }
        acc += g_h[i * D + d];
    }
    if (curg >= 0) atomicAdd(&out[curg * D + d], acc);
}

// ---------------- launch ----------------
extern "C" void kernel_launch(void* const* d_in, const int* in_sizes, int n_in,
                              void* d_out, int out_size) {
    const float* x = nullptr;
    const int* ei = nullptr;
    const int* batch = nullptr;
    const float* We = nullptr; const float* be = nullptr;
    const float* Wg = nullptr; const float* bg = nullptr;

    for (int i = 0; i < n_in; i++) {
        switch (in_sizes[i]) {
            case N_NODES * IN_FEAT:      x     = (const float*)d_in[i]; break;
            case 2 * N_EDGES:            ei    = (const int*)d_in[i];   break;
            case N_NODES:                batch = (const int*)d_in[i];   break;
            case IN_FEAT * D:            We    = (const float*)d_in[i]; break;
            case D:                      be    = (const float*)d_in[i]; break;
            case N_LAYERS * D * D:       Wg    = (const float*)d_in[i]; break;
            case N_LAYERS * D:           bg    = (const float*)d_in[i]; break;
            default: break; // num_graphs scalar etc.
        }
    }
    float* out = (float*)d_out;

    // idempotent, not a stream op — capture-safe; no static guard.
    cudaFuncSetAttribute(k_gemm, cudaFuncAttributeMaxDynamicSharedMemorySize,
                         (D * D + 64 * D) * sizeof(float));

    // --- CSR build ---
    k_zero_int<<<(N_NODES + 255) / 256, 256>>>();
    k_hist<<<(N_EDGES + 255) / 256, 256>>>(ei);
    k_dinv<<<(N_NODES + 255) / 256, 256>>>();
    k_scan<<<1, 1024>>>();
    k_scatter<<<(N_EDGES + 255) / 256, 256>>>(ei);

    // --- expansion ---
    k_expand<<<4096, D>>>(x, We, be);

    // --- layers ---
    int gemm_blocks = (N_NODES + 63) / 64;
    size_t gemm_smem = (size_t)(D * D + 64 * D) * sizeof(float);
    for (int l = 0; l < N_LAYERS; l++) {
        k_gemm<<<gemm_blocks, 256, gemm_smem>>>(Wg + (size_t)l * D * D);
        k_aggregate<<<N_NODES, D>>>(bg + (size_t)l * D);
    }

    // --- pooling ---
    k_zero_out<<<(out_size + 255) / 256, 256>>>(out, out_size);
    k_pool<<<(N_NODES + NODES_PER_BLOCK - 1) / NODES_PER_BLOCK, D>>>(batch, out);
}

// round 4
// speedup vs baseline: 1.6473x; 1.6473x over previous
#include <cuda_runtime.h>
#include <cuda_bf16.h>
#include <math.h>
#include <stdint.h>

#define N_NODES 100000
#define N_EDGES 400000
#define D 128
#define N_GRAPHS 4096
#define N_LAYERS 5
#define IN_FEAT 11

// ---------------- scratch (device globals; no allocations) ----------------
__device__ float g_h[N_NODES * D];
__device__ float g_t[N_NODES * D];
__device__ float g_dinv[N_NODES];
__device__ float g_eval[N_EDGES];
__device__ int   g_cnt[N_NODES];
__device__ int   g_fill[N_NODES];
__device__ int   g_rowptr[N_NODES + 1];
__device__ int   g_col[N_EDGES];

// ---------------- preprocessing ----------------
__global__ void k_zero_int() {
    int i = blockIdx.x * blockDim.x + threadIdx.x;
    if (i < N_NODES) { g_cnt[i] = 0; g_fill[i] = 0; }
}

__global__ void k_hist(const int* __restrict__ ei) {
    int e = blockIdx.x * blockDim.x + threadIdx.x;
    if (e < N_EDGES) atomicAdd(&g_cnt[ei[N_EDGES + e]], 1);
}

__global__ void k_dinv() {
    int i = blockIdx.x * blockDim.x + threadIdx.x;
    if (i < N_NODES) g_dinv[i] = rsqrtf((float)g_cnt[i] + 2.0f);
}

#define SCAN_CHUNK 256
#define NPART ((N_NODES + SCAN_CHUNK - 1) / SCAN_CHUNK)   // 391
__device__ int g_part[NPART];

__global__ void k_partials() {
    __shared__ int sh[256];
    int t = threadIdx.x, i = blockIdx.x * 256 + t;
    sh[t] = (i < N_NODES) ? g_cnt[i] : 0;
    __syncthreads();
    for (int o = 128; o > 0; o >>= 1) { if (t < o) sh[t] += sh[t + o]; __syncthreads(); }
    if (t == 0) g_part[blockIdx.x] = sh[0];
}

__global__ void k_scanpart() {   // 1 block, 512 threads (NPART=391 < 512)
    __shared__ int sh[512];
    int t = threadIdx.x;
    int v = (t < NPART) ? g_part[t] : 0;
    sh[t] = v;
    __syncthreads();
    for (int o = 1; o < 512; o <<= 1) {
        int x = (t >= o) ? sh[t - o] : 0;
        __syncthreads();
        sh[t] += x;
        __syncthreads();
    }
    if (t < NPART) g_part[t] = sh[t] - v;   // exclusive
    if (t == 0) g_rowptr[N_NODES] = N_EDGES;
}

__global__ void k_rowptr() {
    __shared__ int sh[256];
    int t = threadIdx.x, i = blockIdx.x * 256 + t;
    int v = (i < N_NODES) ? g_cnt[i] : 0;
    sh[t] = v;
    __syncthreads();
    for (int o = 1; o < 256; o <<= 1) {
        int x = (t >= o) ? sh[t - o] : 0;
        __syncthreads();
        sh[t] += x;
        __syncthreads();
    }
    if (i < N_NODES) g_rowptr[i] = sh[t] - v + g_part[blockIdx.x];
}

__global__ void k_scatter(const int* __restrict__ ei) {
    int e = blockIdx.x * blockDim.x + threadIdx.x;
    if (e < N_EDGES) {
        int s = ei[e];
        int d = ei[N_EDGES + e];
        int pos = g_rowptr[d] + atomicAdd(&g_fill[d], 1);
        g_col[pos]  = s;
        g_eval[pos] = g_dinv[s] * g_dinv[d];
    }
}

// ---------------- expansion: h = log1p(x) @ We + be ----------------
__global__ void k_expand(const float* __restrict__ x,
                         const float* __restrict__ We,
                         const float* __restrict__ be) {
    __shared__ float sW[IN_FEAT * D];
    __shared__ float lx[IN_FEAT];
    int d = threadIdx.x;
    #pragma unroll
    for (int k = 0; k < IN_FEAT; k++) sW[k * D + d] = We[k * D + d];
    float bias = be[d];
    for (int i = blockIdx.x; i < N_NODES; i += gridDim.x) {
        if (d < IN_FEAT) lx[d] = log1pf(x[i * IN_FEAT + d]);
        __syncthreads();
        float acc = bias;
        #pragma unroll
        for (int k = 0; k < IN_FEAT; k++) acc = fmaf(lx[k], sW[k * D + d], acc);
        g_h[i * D + d] = acc;
        __syncthreads();
    }
}

// ---------------- mma.sync TF32 helpers ----------------
__device__ __forceinline__ float to_tf32(float x) {
    float r;
    asm("cvt.rna.tf32.f32 %0, %1;" : "=f"(r) : "f"(x));
    return r;
}

__device__ __forceinline__ void mma8(float* c, const uint32_t* a, const uint32_t* b) {
    asm volatile(
        "mma.sync.aligned.m16n8k8.row.col.f32.tf32.tf32.f32 "
        "{%0,%1,%2,%3}, {%4,%5,%6,%7}, {%8,%9}, {%0,%1,%2,%3};"
        : "+f"(c[0]), "+f"(c[1]), "+f"(c[2]), "+f"(c[3])
        : "r"(a[0]), "r"(a[1]), "r"(a[2]), "r"(a[3]), "r"(b[0]), "r"(b[1]));
}

// ---------------- TF32 tensor-core GEMM: t = h @ W ----------------
// CTA: 128 rows x 128 cols, 8 warps (4 warp-rows x 2 warp-cols), warp = 32x64.
#define AS 132   // padded smem stride (floats) to avoid LDS bank conflicts

__global__ __launch_bounds__(256) void k_gemm_mma(const float* __restrict__ W) {
    extern __shared__ float sm[];
    float* sA = sm;              // [128][AS]
    float* sB = sm + 128 * AS;   // [128][AS]  (k-major: sB[k][n])

    int tid = threadIdx.x, wid = tid >> 5, lane = tid & 31;
    int wrow = wid & 3, wcol = wid >> 2;       // warp tile origin: (wrow*32, wcol*64)
    int row0 = blockIdx.x * 128;

    // fill A (h rows, tf32-rounded)
    {
        const float4* H4 = (const float4*)g_h;
        #pragma unroll
        for (int i = tid; i < 128 * 32; i += 256) {
            int r = i >> 5, k4 = i & 31;
            int gr = row0 + r;
            float4 v = (gr < N_NODES) ? H4[(size_t)gr * 32 + k4]
                                      : make_float4(0.f, 0.f, 0.f, 0.f);
            v.x = to_tf32(v.x); v.y = to_tf32(v.y);
            v.z = to_tf32(v.z); v.w = to_tf32(v.w);
            *(float4*)&sA[r * AS + k4 * 4] = v;
        }
    }
    // fill B = W (row-major [k][n], tf32-rounded)
    {
        const float4* W4 = (const float4*)W;
        #pragma unroll
        for (int i = tid; i < 128 * 32; i += 256) {
            int k = i >> 5, n4 = i & 31;
            float4 v = W4[k * 32 + n4];
            v.x = to_tf32(v.x); v.y = to_tf32(v.y);
            v.z = to_tf32(v.z); v.w = to_tf32(v.w);
            *(float4*)&sB[k * AS + n4 * 4] = v;
        }
    }
    __syncthreads();

    float acc[2][8][4];
    #pragma unroll
    for (int mi = 0; mi < 2; mi++)
        #pragma unroll
        for (int ni = 0; ni < 8; ni++)
            #pragma unroll
            for (int j = 0; j < 4; j++) acc[mi][ni][j] = 0.f;

    int qr = lane >> 2, qc = lane & 3;   // quad row / col within fragment

    #pragma unroll 4
    for (int k0 = 0; k0 < 128; k0 += 8) {
        uint32_t a[2][4];
        #pragma unroll
        for (int mi = 0; mi < 2; mi++) {
            int r = wrow * 32 + mi * 16 + qr;
            a[mi][0] = __float_as_uint(sA[r * AS + k0 + qc]);
            a[mi][1] = __float_as_uint(sA[(r + 8) * AS + k0 + qc]);
            a[mi][2] = __float_as_uint(sA[r * AS + k0 + 4 + qc]);
            a[mi][3] = __float_as_uint(sA[(r + 8) * AS + k0 + 4 + qc]);
        }
        uint32_t b[8][2];
        #pragma unroll
        for (int ni = 0; ni < 8; ni++) {
            int n = wcol * 64 + ni * 8 + qr;
            b[ni][0] = __float_as_uint(sB[(k0 + qc) * AS + n]);
            b[ni][1] = __float_as_uint(sB[(k0 + 4 + qc) * AS + n]);
        }
        #pragma unroll
        for (int mi = 0; mi < 2; mi++)
            #pragma unroll
            for (int ni = 0; ni < 8; ni++)
                mma8(acc[mi][ni], a[mi], b[ni]);
    }

    // epilogue: write t
    #pragma unroll
    for (int mi = 0; mi < 2; mi++) {
        int r = row0 + wrow * 32 + mi * 16 + qr;
        #pragma unroll
        for (int half = 0; half < 2; half++) {
            int gr = r + half * 8;
            if (gr < N_NODES) {
                #pragma unroll
                for (int ni = 0; ni < 8; ni++) {
                    int n = wcol * 64 + ni * 8 + qc * 2;
                    float2 v = make_float2(acc[mi][ni][half * 2], acc[mi][ni][half * 2 + 1]);
                    *(float2*)&g_t[(size_t)gr * D + n] = v;
                }
            }
        }
    }
}

// ---------------- aggregate: h += relu(self + neighbor sum + bias) --------
// warp per node, lane handles one float4 (16 B) of the 512-B row
__global__ __launch_bounds__(256) void k_aggregate(const float* __restrict__ bgl) {
    int gw = (blockIdx.x * blockDim.x + threadIdx.x) >> 5;
    int lane = threadIdx.x & 31;
    if (gw >= N_NODES) return;
    const float4* T4 = (const float4*)g_t;
    float4* H4 = (float4*)g_h;

    float4 b4 = ((const float4*)bgl)[lane];
    float dv = g_dinv[gw];
    float sn = 2.0f * dv * dv;
    float4 t0 = T4[(size_t)gw * 32 + lane];
    float4 acc = make_float4(fmaf(sn, t0.x, b4.x), fmaf(sn, t0.y, b4.y),
                             fmaf(sn, t0.z, b4.z), fmaf(sn, t0.w, b4.w));

    int s0 = g_rowptr[gw], s1 = g_rowptr[gw + 1];
    int e = s0;
    for (; e + 1 < s1; e += 2) {
        float w0 = g_eval[e],     w1 = g_eval[e + 1];
        int   c0 = g_col[e],      c1 = g_col[e + 1];
        float4 v0 = T4[(size_t)c0 * 32 + lane];
        float4 v1 = T4[(size_t)c1 * 32 + lane];
        acc.x = fmaf(w0, v0.x, acc.x); acc.y = fmaf(w0, v0.y, acc.y);
        acc.z = fmaf(w0, v0.z, acc.z); acc.w = fmaf(w0, v0.w, acc.w);
        acc.x = fmaf(w1, v1.x, acc.x); acc.y = fmaf(w1, v1.y, acc.y);
        acc.z = fmaf(w1, v1.z, acc.z); acc.w = fmaf(w1, v1.w, acc.w);
    }
    if (e < s1) {
        float w0 = g_eval[e]; int c0 = g_col[e];
        float4 v0 = T4[(size_t)c0 * 32 + lane];
        acc.x = fmaf(w0, v0.x, acc.x); acc.y = fmaf(w0, v0.y, acc.y);
        acc.z = fmaf(w0, v0.z, acc.z); acc.w = fmaf(w0, v0.w, acc.w);
    }

    float4 h = H4[(size_t)gw * 32 + lane];
    h.x += fmaxf(acc.x, 0.f); h.y += fmaxf(acc.y, 0.f);
    h.z += fmaxf(acc.z, 0.f); h.w += fmaxf(acc.w, 0.f);
    H4[(size_t)gw * 32 + lane] = h;
}

// ---------------- pooling ----------------
__global__ void k_zero_out(float* __restrict__ out, int n) {
    int i = blockIdx.x * blockDim.x + threadIdx.x;
    if (i < n) out[i] = 0.f;
}

#define NODES_PER_BLOCK 16
__global__ void k_pool(const int* __restrict__ batch, float* __restrict__ out) {
    int n0 = blockIdx.x * NODES_PER_BLOCK;
    int d = threadIdx.x;
    float acc = 0.f;
    int curg = -1;
    for (int j = 0; j < NODES_PER_BLOCK; j++) {
        int i = n0 + j;
        if (i >= N_NODES) break;
        int g = batch[i];
        if (g != curg) {
            if (curg >= 0) atomicAdd(&out[curg * D + d], acc);
            curg = g; acc = 0.f;
        }
        acc += g_h[i * D + d];
    }
    if (curg >= 0) atomicAdd(&out[curg * D + d], acc);
}

// ---------------- launch ----------------
extern "C" void kernel_launch(void* const* d_in, const int* in_sizes, int n_in,
                              void* d_out, int out_size) {
    const float* x = nullptr;
    const int* ei = nullptr;
    const int* batch = nullptr;
    const float* We = nullptr; const float* be = nullptr;
    const float* Wg = nullptr; const float* bg = nullptr;

    for (int i = 0; i < n_in; i++) {
        switch (in_sizes[i]) {
            case N_NODES * IN_FEAT:  x     = (const float*)d_in[i]; break;
            case 2 * N_EDGES:        ei    = (const int*)d_in[i];   break;
            case N_NODES:            batch = (const int*)d_in[i];   break;
            case IN_FEAT * D:        We    = (const float*)d_in[i]; break;
            case D:                  be    = (const float*)d_in[i]; break;
            case N_LAYERS * D * D:   Wg    = (const float*)d_in[i]; break;
            case N_LAYERS * D:       bg    = (const float*)d_in[i]; break;
            default: break;
        }
    }
    float* out = (float*)d_out;

    size_t gemm_smem = (size_t)2 * 128 * AS * sizeof(float);   // 135168
    cudaFuncSetAttribute(k_gemm_mma, cudaFuncAttributeMaxDynamicSharedMemorySize,
                         (int)gemm_smem);

    // --- CSR build ---
    k_zero_int<<<(N_NODES + 255) / 256, 256>>>();
    k_hist<<<(N_EDGES + 255) / 256, 256>>>(ei);
    k_dinv<<<(N_NODES + 255) / 256, 256>>>();
    k_partials<<<NPART, 256>>>();
    k_scanpart<<<1, 512>>>();
    k_rowptr<<<NPART, 256>>>();
    k_scatter<<<(N_EDGES + 255) / 256, 256>>>(ei);

    // --- expansion ---
    k_expand<<<4096, D>>>(x, We, be);

    // --- layers ---
    int gemm_blocks = (N_NODES + 127) / 128;   // 782
    for (int l = 0; l < N_LAYERS; l++) {
        k_gemm_mma<<<gemm_blocks, 256, gemm_smem>>>(Wg + (size_t)l * D * D);
        k_aggregate<<<(N_NODES * 32 + 255) / 256, 256>>>(bg + (size_t)l * D);
    }

    // --- pooling ---
    k_zero_out<<<(out_size + 255) / 256, 256>>>(out, out_size);
    k_pool<<<(N_NODES + NODES_PER_BLOCK - 1) / NODES_PER_BLOCK, D>>>(batch, out);
}